// round 12
// baseline (speedup 1.0000x reference)
#include <cuda_runtime.h>
#include <cstdint>

// message_pass: out = prelu(prelu([x_i|x_j|ea] @ W1 + b1, a) @ W2 + b2, a)
// E*H=500000 rows, d_in=144, HID=128, C=64. fp32 I/O, TF32 mma.sync.
// MT=128 rows/tile, 256 threads, persistent CTAs.
// k-slot permutation: mma slot t <-> logical k 2t, slot t+4 <-> 2t+1 (A and B
// packed consistently), enabling LDG.64 A-loads and LDS.64 H-loads.

#define HSTR 136                           // H row stride (== 8 mod 32: conflict-free)
#define OFF_W1F 0                          // 73728 B : W1 pair-packed fragments
#define OFF_W2F 73728                      // 32768 B : W2 pair-packed fragments
#define OFF_H   106496                     // 128*HSTR*4 = 69632 B
#define OFF_B1  (OFF_H + 128*HSTR*4)       // 176128
#define OFF_B2  (OFF_B1 + 512)
#define SMEM_BYTES (OFF_B2 + 256)          // 176896 B

__device__ __forceinline__ uint32_t f2tf32(float x) {
    uint32_t r;
    asm("cvt.rna.tf32.f32 %0, %1;" : "=r"(r) : "f"(x));
    return r;
}

__device__ __forceinline__ void mma_tf32(float* d, const uint32_t* a,
                                         uint32_t b0, uint32_t b1) {
    asm volatile(
        "mma.sync.aligned.m16n8k8.row.col.f32.tf32.tf32.f32 "
        "{%0,%1,%2,%3}, {%4,%5,%6,%7}, {%8,%9}, {%0,%1,%2,%3};"
        : "+f"(d[0]), "+f"(d[1]), "+f"(d[2]), "+f"(d[3])
        : "r"(a[0]), "r"(a[1]), "r"(a[2]), "r"(a[3]), "r"(b0), "r"(b1));
}

// load A fragments for k-step s into pf[4] (4 row offsets: base+0,8,16,24)
__device__ __forceinline__ void loadA(float2* pf,
                                      const float* __restrict__ xi,
                                      const float* __restrict__ xj,
                                      const float* __restrict__ ea,
                                      const int* rr, int s, int t2) {
    #pragma unroll
    for (int j = 0; j < 4; ++j) {
        const float* p;
        if (s < 8)       p = xi + rr[j] * 64 + 8 * s       + t2;
        else if (s < 16) p = xj + rr[j] * 64 + 8 * s - 64  + t2;
        else             p = ea + rr[j] * 16 + 8 * s - 128 + t2;
        pf[j] = *(const float2*)p;
    }
}

__global__ __launch_bounds__(256, 1)
void message_pass_22548578304895_kernel(
    const float* __restrict__ xi, const float* __restrict__ xj,
    const float* __restrict__ ea, const float* __restrict__ W1g,
    const float* __restrict__ b1g, const float* __restrict__ W2g,
    const float* __restrict__ b2g, const float* __restrict__ alphap,
    float* __restrict__ out, int nrows, int ntiles)
{
    extern __shared__ char smem[];
    float* smf = (float*)smem;
    const int tid  = threadIdx.x;
    const int w    = tid >> 5;
    const int lane = tid & 31;
    const int g    = lane >> 2;
    const int t    = lane & 3;
    const int t2   = 2 * t;
    const int r1 = w >> 1, c1 = w & 1;     // layer1: 4 row-slabs(32) x 2 col-halves(64)
    const int r2 = w & 3,  c2 = w >> 2;    // layer2: 4 row-slabs(32) x 2 col-halves(32)
    const float alpha = __ldg(alphap);

    // ---- pack W1 fragments: pair p=(s,pp); lane(lt,lg);
    //      {b0,b1} x {atom 2pp, atom 2pp+1}; b0 = W[8s+2lt][col], b1 = W[8s+2lt+1][col]
    for (int idx = tid; idx < 4608; idx += 256) {
        int pg_ = idx >> 5;
        int s = pg_ >> 3, pp = pg_ & 7;
        int ll = idx & 31, lt = ll & 3, lg = ll >> 2;
        int row0 = 8 * s + 2 * lt, col0 = 16 * pp + lg;
        uint4 v;
        v.x = f2tf32(W1g[row0 * 128 + col0]);
        v.y = f2tf32(W1g[(row0 + 1) * 128 + col0]);
        v.z = f2tf32(W1g[row0 * 128 + col0 + 8]);
        v.w = f2tf32(W1g[(row0 + 1) * 128 + col0 + 8]);
        *(uint4*)(smem + OFF_W1F + idx * 16) = v;
    }
    for (int idx = tid; idx < 2048; idx += 256) {
        int pg_ = idx >> 5;
        int s = pg_ >> 2, pp = pg_ & 3;
        int ll = idx & 31, lt = ll & 3, lg = ll >> 2;
        int row0 = 8 * s + 2 * lt, col0 = 16 * pp + lg;
        uint4 v;
        v.x = f2tf32(W2g[row0 * 64 + col0]);
        v.y = f2tf32(W2g[(row0 + 1) * 64 + col0]);
        v.z = f2tf32(W2g[row0 * 64 + col0 + 8]);
        v.w = f2tf32(W2g[(row0 + 1) * 64 + col0 + 8]);
        *(uint4*)(smem + OFF_W2F + idx * 16) = v;
    }
    if (tid < 128) smf[OFF_B1 / 4 + tid] = b1g[tid];
    if (tid < 64)  smf[OFF_B2 / 4 + tid] = b2g[tid];
    __syncthreads();

    int rr[4];
    float2 pf[2][4];

    // prologue prefetch for first tile
    {
        int tl = ((int)blockIdx.x < ntiles) ? (int)blockIdx.x : 0;
        int base = tl * 128 + r1 * 32 + g;
        #pragma unroll
        for (int j = 0; j < 4; ++j) {
            int r = base + 8 * j;
            rr[j] = (r < nrows) ? r : (nrows - 1);
        }
        loadA(pf[0], xi, xj, ea, rr, 0, t2);
        loadA(pf[1], xi, xj, ea, rr, 1, t2);
    }

    for (int tile = blockIdx.x; tile < ntiles; tile += gridDim.x) {
        // ================= layer 1: [128,144] @ [144,128] =================
        float acc1[2][8][4];
        #pragma unroll
        for (int f = 0; f < 2; ++f)
            #pragma unroll
            for (int a8 = 0; a8 < 8; ++a8)
                #pragma unroll
                for (int r = 0; r < 4; ++r) acc1[f][a8][r] = 0.f;

        #pragma unroll
        for (int s = 0; s < 18; ++s) {
            int st = s & 1;
            uint32_t a[2][4];
            #pragma unroll
            for (int f = 0; f < 2; ++f) {
                a[f][0] = f2tf32(pf[st][2 * f].x);       // slot t     = k 2t   (row g)
                a[f][2] = f2tf32(pf[st][2 * f].y);       // slot t+4   = k 2t+1 (row g)
                a[f][1] = f2tf32(pf[st][2 * f + 1].x);   // row g+8
                a[f][3] = f2tf32(pf[st][2 * f + 1].y);
            }
            if (s + 2 < 18) loadA(pf[st], xi, xj, ea, rr, s + 2, t2);
            #pragma unroll
            for (int ap = 0; ap < 4; ++ap) {
                uint4 B = *(const uint4*)(smem + OFF_W1F
                          + (((s * 8) + c1 * 4 + ap) * 32 + lane) * 16);
                mma_tf32(acc1[0][2 * ap],     a[0], B.x, B.y);
                mma_tf32(acc1[0][2 * ap + 1], a[0], B.z, B.w);
                mma_tf32(acc1[1][2 * ap],     a[1], B.x, B.y);
                mma_tf32(acc1[1][2 * ap + 1], a[1], B.z, B.w);
            }
        }

        // ---- epilogue 1: bias + prelu + rna(tf32) -> H smem (row-major) ----
        #pragma unroll
        for (int f = 0; f < 2; ++f) {
            #pragma unroll
            for (int at = 0; at < 8; ++at) {
                int col = c1 * 64 + at * 8 + t2;
                float bx = smf[OFF_B1 / 4 + col], by = smf[OFF_B1 / 4 + col + 1];
                #pragma unroll
                for (int pr = 0; pr < 2; ++pr) {
                    int row = r1 * 32 + f * 16 + g + pr * 8;
                    float v0 = acc1[f][at][2 * pr]     + bx;
                    float v1 = acc1[f][at][2 * pr + 1] + by;
                    v0 = (v0 >= 0.f) ? v0 : alpha * v0;
                    v1 = (v1 >= 0.f) ? v1 : alpha * v1;
                    float2 stv;
                    stv.x = __uint_as_float(f2tf32(v0));
                    stv.y = __uint_as_float(f2tf32(v1));
                    *(float2*)(smf + OFF_H / 4 + row * HSTR + col) = stv;
                }
            }
        }
        __syncthreads();   // H complete

        // ---- cross-tile prefetch of next tile's first two k-steps ----
        {
            int nt = tile + gridDim.x;
            int tl = (nt < ntiles) ? nt : tile;
            int base = tl * 128 + r1 * 32 + g;
            #pragma unroll
            for (int j = 0; j < 4; ++j) {
                int r = base + 8 * j;
                rr[j] = (r < nrows) ? r : (nrows - 1);
            }
            loadA(pf[0], xi, xj, ea, rr, 0, t2);
            loadA(pf[1], xi, xj, ea, rr, 1, t2);
        }

        // ================= layer 2: [128,128] @ [128,64] =================
        float acc2[2][4][4];
        #pragma unroll
        for (int f = 0; f < 2; ++f)
            #pragma unroll
            for (int a4 = 0; a4 < 4; ++a4)
                #pragma unroll
                for (int r = 0; r < 4; ++r) acc2[f][a4][r] = 0.f;

        #pragma unroll
        for (int s = 0; s < 16; ++s) {
            uint32_t a[2][4];
            #pragma unroll
            for (int f = 0; f < 2; ++f) {
                const float* hp = smf + OFF_H / 4
                                + (r2 * 32 + f * 16 + g) * HSTR + 8 * s + t2;
                float2 lo = *(const float2*)hp;              // row g
                float2 hi = *(const float2*)(hp + 8 * HSTR); // row g+8
                a[f][0] = __float_as_uint(lo.x);
                a[f][2] = __float_as_uint(lo.y);
                a[f][1] = __float_as_uint(hi.x);
                a[f][3] = __float_as_uint(hi.y);
            }
            #pragma unroll
            for (int ap = 0; ap < 2; ++ap) {
                uint4 B = *(const uint4*)(smem + OFF_W2F
                          + ((s * 4 + c2 * 2 + ap) * 32 + lane) * 16);
                mma_tf32(acc2[0][2 * ap],     a[0], B.x, B.y);
                mma_tf32(acc2[0][2 * ap + 1], a[0], B.z, B.w);
                mma_tf32(acc2[1][2 * ap],     a[1], B.x, B.y);
                mma_tf32(acc2[1][2 * ap + 1], a[1], B.z, B.w);
            }
        }
        __syncthreads();   // H reads done; next epi1 may overwrite

        // ---- epilogue 2: bias + prelu -> gmem (float2, full 32B sectors) ----
        #pragma unroll
        for (int f = 0; f < 2; ++f) {
            #pragma unroll
            for (int at = 0; at < 4; ++at) {
                int col = c2 * 32 + at * 8 + t2;
                float bx = smf[OFF_B2 / 4 + col], by = smf[OFF_B2 / 4 + col + 1];
                #pragma unroll
                for (int pr = 0; pr < 2; ++pr) {
                    int row  = r2 * 32 + f * 16 + g + pr * 8;
                    int grow = tile * 128 + row;
                    float v0 = acc2[f][at][2 * pr]     + bx;
                    float v1 = acc2[f][at][2 * pr + 1] + by;
                    v0 = (v0 >= 0.f) ? v0 : alpha * v0;
                    v1 = (v1 >= 0.f) ? v1 : alpha * v1;
                    if (grow < nrows)
                        *(float2*)(out + (size_t)grow * 64 + col) = make_float2(v0, v1);
                }
            }
        }
    }
}

extern "C" void kernel_launch(void* const* d_in, const int* in_sizes, int n_in,
                              void* d_out, int out_size) {
    const float* xi     = (const float*)d_in[0];
    const float* xj     = (const float*)d_in[1];
    const float* ea     = (const float*)d_in[2];
    const float* W1     = (const float*)d_in[3];
    const float* b1     = (const float*)d_in[4];
    const float* W2     = (const float*)d_in[5];
    const float* b2     = (const float*)d_in[6];
    const float* alphap = (const float*)d_in[7];
    float* out = (float*)d_out;

    int nrows  = in_sizes[0] / 64;                 // E*H
    int ntiles = (nrows + 127) / 128;

    int dev = 0, sms = 148;
    cudaGetDevice(&dev);
    cudaDeviceGetAttribute(&sms, cudaDevAttrMultiProcessorCount, dev);

    cudaFuncSetAttribute(message_pass_22548578304895_kernel,
                         cudaFuncAttributeMaxDynamicSharedMemorySize, SMEM_BYTES);

    int grid = sms < ntiles ? sms : ntiles;
    message_pass_22548578304895_kernel<<<grid, 256, SMEM_BYTES>>>(
        xi, xj, ea, W1, b1, W2, b2, alphap, out, nrows, ntiles);
}